// round 1
// baseline (speedup 1.0000x reference)
#include <cuda_runtime.h>
#include <cuda_bf16.h>
#include <math.h>

// Problem dims (fixed)
#define T_DIM 8192
#define M_DIM 1024
#define N_DIM 2048

// ---------------- scratch + barrier state (no allocations allowed) ----------
__device__ float g_pre[(size_t)T_DIM * N_DIM];   // 64 MB scratch: pre = X@W_ih^T + b
__device__ float g_h0[N_DIM];                    // zero-initialized, never written -> h_{-1}=0
__device__ unsigned g_count;
__device__ unsigned g_phase;

__global__ void init_barrier_kernel() {
    g_count = 0u;
    g_phase = 0u;
}

// ---------------- Kernel A: pre = X @ W_ih^T + (b_ih + b_hh) ----------------
// C[t,n] = sum_k X[t,k] * W_ih[n,k]   (both operands K-major row dots)
// 128x128 tile, BK=8, 256 threads, 8x8 per-thread microtile.
__global__ __launch_bounds__(256) void gemm_pre_kernel(
    const float* __restrict__ X,
    const float* __restrict__ Wih,
    const float* __restrict__ b_ih,
    const float* __restrict__ b_hh)
{
    __shared__ float As[8][128];
    __shared__ float Bs[8][128];

    const int tx   = threadIdx.x;
    const int row0 = blockIdx.y * 128;   // t tile
    const int col0 = blockIdx.x * 128;   // n tile

    const int lr = tx >> 1;              // 0..127 (tile row for loading)
    const int lc = (tx & 1) << 2;        // 0 or 4 (k offset for loading)
    const int trow = (tx >> 4) << 3;     // compute microtile row
    const int tcol = (tx & 15) << 3;     // compute microtile col

    float acc[8][8];
#pragma unroll
    for (int i = 0; i < 8; i++)
#pragma unroll
        for (int j = 0; j < 8; j++) acc[i][j] = 0.0f;

    const float* Xp = X   + (size_t)(row0 + lr) * M_DIM + lc;
    const float* Wp = Wih + (size_t)(col0 + lr) * M_DIM + lc;

    for (int k0 = 0; k0 < M_DIM; k0 += 8) {
        float4 a = *(const float4*)(Xp + k0);
        float4 b = *(const float4*)(Wp + k0);
        As[lc + 0][lr] = a.x; As[lc + 1][lr] = a.y;
        As[lc + 2][lr] = a.z; As[lc + 3][lr] = a.w;
        Bs[lc + 0][lr] = b.x; Bs[lc + 1][lr] = b.y;
        Bs[lc + 2][lr] = b.z; Bs[lc + 3][lr] = b.w;
        __syncthreads();

#pragma unroll
        for (int k = 0; k < 8; k++) {
            float ar[8], br[8];
#pragma unroll
            for (int i = 0; i < 8; i++) ar[i] = As[k][trow + i];
#pragma unroll
            for (int j = 0; j < 8; j++) br[j] = Bs[k][tcol + j];
#pragma unroll
            for (int i = 0; i < 8; i++)
#pragma unroll
                for (int j = 0; j < 8; j++)
                    acc[i][j] = fmaf(ar[i], br[j], acc[i][j]);
        }
        __syncthreads();
    }

    float bias[8];
#pragma unroll
    for (int j = 0; j < 8; j++)
        bias[j] = b_ih[col0 + tcol + j] + b_hh[col0 + tcol + j];

#pragma unroll
    for (int i = 0; i < 8; i++) {
        float* out = &g_pre[(size_t)(row0 + trow + i) * N_DIM + col0 + tcol];
#pragma unroll
        for (int j = 0; j < 8; j++) out[j] = acc[i][j] + bias[j];
    }
}

// ---------------- Kernel B: persistent recurrence ---------------------------
// 128 CTAs (all simultaneously resident on 148 SMs -> custom grid barrier is safe).
// CTA b owns rows [16b, 16b+16) of W_hh, held ENTIRELY IN REGISTERS:
//   thread j (of 256) holds W_hh[r][8j .. 8j+7] for all 16 rows (128 regs).
// Per step: load h_{t-1}[8j..8j+7] (global, L2-resident), 128 FFMA,
// smem partial-sum matrix part[16][256], warp-level reduction (2 rows/warp),
// tanh + store, threadfence, global sense barrier.
#define GR   128
#define RPB  16
#define RTHR 256

__global__ __launch_bounds__(RTHR, 1) void recur_kernel(
    const float* __restrict__ Whh,
    float* __restrict__ Y)
{
    const int tid  = threadIdx.x;
    const int base = blockIdx.x * RPB;
    const int warp = tid >> 5;
    const int lane = tid & 31;

    // Load this thread's weight block into registers (16 rows x 8 cols).
    float w[RPB][8];
#pragma unroll
    for (int r = 0; r < RPB; r++) {
        const float4* p = (const float4*)&Whh[(size_t)(base + r) * N_DIM + tid * 8];
        float4 a = p[0], b = p[1];
        w[r][0] = a.x; w[r][1] = a.y; w[r][2] = a.z; w[r][3] = a.w;
        w[r][4] = b.x; w[r][5] = b.y; w[r][6] = b.z; w[r][7] = b.w;
    }

    __shared__ float part[RPB][RTHR];   // 16 KB

    const float* hp = g_h0;             // h_{-1} = 0

    for (int t = 0; t < T_DIM; t++) {
        // h_{t-1} slice for this thread's columns
        const float4* hv = (const float4*)(hp + tid * 8);
        float4 h0 = hv[0];
        float4 h1 = hv[1];

#pragma unroll
        for (int r = 0; r < RPB; r++) {
            float acc;
            acc = w[r][0] * h0.x;
            acc = fmaf(w[r][1], h0.y, acc);
            acc = fmaf(w[r][2], h0.z, acc);
            acc = fmaf(w[r][3], h0.w, acc);
            acc = fmaf(w[r][4], h1.x, acc);
            acc = fmaf(w[r][5], h1.y, acc);
            acc = fmaf(w[r][6], h1.z, acc);
            acc = fmaf(w[r][7], h1.w, acc);
            part[r][tid] = acc;
        }
        __syncthreads();

        // Each warp reduces 2 rows: 256 partials -> 1 value.
#pragma unroll
        for (int rr = 0; rr < 2; rr++) {
            const int r = warp * 2 + rr;
            float4 x = *(const float4*)&part[r][lane * 4];
            float4 y = *(const float4*)&part[r][128 + lane * 4];
            float s = (x.x + x.y) + (x.z + x.w) + (y.x + y.y) + (y.z + y.w);
#pragma unroll
            for (int o = 16; o > 0; o >>= 1)
                s += __shfl_down_sync(0xffffffffu, s, o);
            if (lane == 0) {
                float v = tanhf(s + g_pre[(size_t)t * N_DIM + base + r]);
                Y[(size_t)t * N_DIM + base + r] = v;
            }
        }

        __threadfence();       // make Y row t visible device-wide
        __syncthreads();       // all warps done (also fences are issued)

        if (tid == 0) {
            unsigned arr = atomicAdd(&g_count, 1u);
            if (arr == GR - 1u) {
                atomicExch(&g_count, 0u);   // all arrived; reset before release
                __threadfence();
                atomicAdd(&g_phase, 1u);    // release phase t+1
            } else {
                while (*(volatile unsigned*)&g_phase < (unsigned)(t + 1)) { }
            }
        }
        __syncthreads();

        hp = Y + (size_t)t * N_DIM;
    }
}

// ---------------- launch ----------------------------------------------------
extern "C" void kernel_launch(void* const* d_in, const int* in_sizes, int n_in,
                              void* d_out, int out_size)
{
    const float* X    = (const float*)d_in[0];  // (T, M)
    const float* Wih  = (const float*)d_in[1];  // (N, M)
    const float* Whh  = (const float*)d_in[2];  // (N, N)
    const float* b_ih = (const float*)d_in[3];  // (N,)
    const float* b_hh = (const float*)d_in[4];  // (N,)
    float* Y = (float*)d_out;                   // (T, N)

    init_barrier_kernel<<<1, 1>>>();

    dim3 ggrid(N_DIM / 128, T_DIM / 128);       // (16, 64)
    gemm_pre_kernel<<<ggrid, 256>>>(X, Wih, b_ih, b_hh);

    recur_kernel<<<GR, RTHR>>>(Whh, Y);
}

// round 5
// speedup vs baseline: 1.2181x; 1.2181x over previous
#include <cuda_runtime.h>
#include <cuda_bf16.h>
#include <math.h>

// Problem dims (fixed)
#define T_DIM 8192
#define M_DIM 1024
#define N_DIM 2048

#define GR   128     // recurrence CTAs (all resident on 148 SMs)
#define RPB  16      // rows of W_hh per CTA
#define RTHR 256

// ---------------- scratch + sync state (no allocations allowed) -------------
__device__ float g_pre[(size_t)T_DIM * N_DIM];   // 64 MB: pre = X@W_ih^T + b
__device__ float g_h0[N_DIM];                    // static zeros -> h_{-1}
__device__ unsigned g_cnt[T_DIM];                // per-step arrival counters

__global__ void init_cnt_kernel() {
    for (int i = threadIdx.x; i < T_DIM; i += blockDim.x) g_cnt[i] = 0u;
}

// ---------------- Kernel A: pre = X @ W_ih^T + (b_ih + b_hh) ----------------
__global__ __launch_bounds__(256) void gemm_pre_kernel(
    const float* __restrict__ X,
    const float* __restrict__ Wih,
    const float* __restrict__ b_ih,
    const float* __restrict__ b_hh)
{
    __shared__ float As[8][128];
    __shared__ float Bs[8][128];

    const int tx   = threadIdx.x;
    const int row0 = blockIdx.y * 128;   // t tile
    const int col0 = blockIdx.x * 128;   // n tile

    const int lr = tx >> 1;
    const int lc = (tx & 1) << 2;
    const int trow = (tx >> 4) << 3;
    const int tcol = (tx & 15) << 3;

    float acc[8][8];
#pragma unroll
    for (int i = 0; i < 8; i++)
#pragma unroll
        for (int j = 0; j < 8; j++) acc[i][j] = 0.0f;

    const float* Xp = X   + (size_t)(row0 + lr) * M_DIM + lc;
    const float* Wp = Wih + (size_t)(col0 + lr) * M_DIM + lc;

    for (int k0 = 0; k0 < M_DIM; k0 += 8) {
        float4 a = *(const float4*)(Xp + k0);
        float4 b = *(const float4*)(Wp + k0);
        As[lc + 0][lr] = a.x; As[lc + 1][lr] = a.y;
        As[lc + 2][lr] = a.z; As[lc + 3][lr] = a.w;
        Bs[lc + 0][lr] = b.x; Bs[lc + 1][lr] = b.y;
        Bs[lc + 2][lr] = b.z; Bs[lc + 3][lr] = b.w;
        __syncthreads();

#pragma unroll
        for (int k = 0; k < 8; k++) {
            float ar[8], br[8];
#pragma unroll
            for (int i = 0; i < 8; i++) ar[i] = As[k][trow + i];
#pragma unroll
            for (int j = 0; j < 8; j++) br[j] = Bs[k][tcol + j];
#pragma unroll
            for (int i = 0; i < 8; i++)
#pragma unroll
                for (int j = 0; j < 8; j++)
                    acc[i][j] = fmaf(ar[i], br[j], acc[i][j]);
        }
        __syncthreads();
    }

    float bias[8];
#pragma unroll
    for (int j = 0; j < 8; j++)
        bias[j] = b_ih[col0 + tcol + j] + b_hh[col0 + tcol + j];

#pragma unroll
    for (int i = 0; i < 8; i++) {
        float* out = &g_pre[(size_t)(row0 + trow + i) * N_DIM + col0 + tcol];
#pragma unroll
        for (int j = 0; j < 8; j++) out[j] = acc[i][j] + bias[j];
    }
}

// ---------------- fast tanh (MUFU.EX2 based, ~1e-7 rel err) -----------------
__device__ __forceinline__ float fast_tanh(float x) {
    float e = __expf(-2.0f * x);            // EX2; saturates to 0 / inf cleanly
    return __fdividef(2.0f, 1.0f + e) - 1.0f;
}

// ---------------- Kernel B: persistent recurrence ---------------------------
// CTA b owns rows [16b,16b+16) of W_hh in registers as packed f32x2 pairs.
// Per step: prefetch pre (h-independent) -> acquire-poll g_cnt[t-1]==128 ->
// load h -> 4x fma.rn.f32x2 per row -> smem partials -> shfl reduce ->
// tanh -> float2 store -> syncthreads -> red.release arrive on g_cnt[t].
// (No __threadfence needed: Y stores happen-before __syncthreads happen-before
//  tid0's release-red; acquire-pollers observing the count see the Y row.)
__global__ __launch_bounds__(RTHR, 1) void recur_kernel(
    const float* __restrict__ Whh,
    float* __restrict__ Y)
{
    const int tid  = threadIdx.x;
    const int base = blockIdx.x * RPB;
    const int warp = tid >> 5;
    const int lane = tid & 31;

    // Weights: thread holds W_hh[base+r][8*tid .. 8*tid+7] as 4 f32x2 packs.
    unsigned long long w2[RPB][4];
#pragma unroll
    for (int r = 0; r < RPB; r++) {
        const ulonglong2* p =
            (const ulonglong2*)&Whh[(size_t)(base + r) * N_DIM + tid * 8];
        ulonglong2 a = p[0], b = p[1];
        w2[r][0] = a.x; w2[r][1] = a.y; w2[r][2] = b.x; w2[r][3] = b.y;
    }

    __shared__ float part[RPB][RTHR];   // 16 KB

    for (int t = 0; t < T_DIM; t++) {
        // Prefetch pre for this warp's two rows (same addr per warp -> bcast).
        const float2 pre2 =
            *(const float2*)&g_pre[(size_t)t * N_DIM + base + 2 * warp];

        // Single-hop barrier: wait until all 128 CTAs finished step t-1.
        if (t > 0) {
            const unsigned* cp = &g_cnt[t - 1];
            unsigned c;
            do {
                asm volatile("ld.acquire.gpu.global.u32 %0, [%1];"
                             : "=r"(c) : "l"(cp) : "memory");
            } while (c < (unsigned)GR);
        }

        const float* hp = (t == 0) ? g_h0 : (Y + (size_t)(t - 1) * N_DIM);
        const ulonglong2* hq = (const ulonglong2*)(hp + tid * 8);
        ulonglong2 ha = hq[0], hb = hq[1];
        unsigned long long h2[4] = { ha.x, ha.y, hb.x, hb.y };

#pragma unroll
        for (int r = 0; r < RPB; r++) {
            unsigned long long acc;
            asm("mul.rn.f32x2 %0, %1, %2;"
                : "=l"(acc) : "l"(w2[r][0]), "l"(h2[0]));
            asm("fma.rn.f32x2 %0, %1, %2, %3;"
                : "=l"(acc) : "l"(w2[r][1]), "l"(h2[1]), "l"(acc));
            asm("fma.rn.f32x2 %0, %1, %2, %3;"
                : "=l"(acc) : "l"(w2[r][2]), "l"(h2[2]), "l"(acc));
            asm("fma.rn.f32x2 %0, %1, %2, %3;"
                : "=l"(acc) : "l"(w2[r][3]), "l"(h2[3]), "l"(acc));
            float lo, hi;
            asm("mov.b64 {%0, %1}, %2;" : "=f"(lo), "=f"(hi) : "l"(acc));
            part[r][tid] = lo + hi;
        }
        __syncthreads();

        // Warp w reduces rows 2w, 2w+1 (interleaved for ILP; bfly shuffles).
        float s0, s1;
        {
            const int r0 = 2 * warp;
            float4 x0 = *(const float4*)&part[r0][lane * 4];
            float4 y0 = *(const float4*)&part[r0][128 + lane * 4];
            float4 x1 = *(const float4*)&part[r0 + 1][lane * 4];
            float4 y1 = *(const float4*)&part[r0 + 1][128 + lane * 4];
            s0 = ((x0.x + x0.y) + (x0.z + x0.w)) + ((y0.x + y0.y) + (y0.z + y0.w));
            s1 = ((x1.x + x1.y) + (x1.z + x1.w)) + ((y1.x + y1.y) + (y1.z + y1.w));
        }
#pragma unroll
        for (int o = 16; o > 0; o >>= 1) {
            s0 += __shfl_xor_sync(0xffffffffu, s0, o);
            s1 += __shfl_xor_sync(0xffffffffu, s1, o);
        }

        if (lane == 0) {
            float2 v;
            v.x = fast_tanh(s0 + pre2.x);
            v.y = fast_tanh(s1 + pre2.y);
            *(float2*)&Y[(size_t)t * N_DIM + base + 2 * warp] = v;
        }

        __syncthreads();     // all warps' Y stores for step t are done

        if (tid == 0) {
            asm volatile("red.release.gpu.global.add.u32 [%0], %1;"
                         :: "l"(&g_cnt[t]), "r"(1u) : "memory");
        }
        // part[] reuse is safe: next STS happens only after this CTA's own
        // bar above and the global poll at the top of iteration t+1.
    }
}

// ---------------- launch ----------------------------------------------------
extern "C" void kernel_launch(void* const* d_in, const int* in_sizes, int n_in,
                              void* d_out, int out_size)
{
    const float* X    = (const float*)d_in[0];  // (T, M)
    const float* Wih  = (const float*)d_in[1];  // (N, M)
    const float* Whh  = (const float*)d_in[2];  // (N, N)
    const float* b_ih = (const float*)d_in[3];  // (N,)
    const float* b_hh = (const float*)d_in[4];  // (N,)
    float* Y = (float*)d_out;                   // (T, N)

    init_cnt_kernel<<<1, 256>>>();

    dim3 ggrid(N_DIM / 128, T_DIM / 128);       // (16, 64)
    gemm_pre_kernel<<<ggrid, 256>>>(X, Wih, b_ih, b_hh);

    recur_kernel<<<GR, RTHR>>>(Whh, Y);
}

// round 6
// speedup vs baseline: 1.5904x; 1.3056x over previous
#include <cuda_runtime.h>
#include <cuda_bf16.h>
#include <math.h>

// Problem dims (fixed)
#define T_DIM 8192
#define M_DIM 1024
#define N_DIM 2048

#define GR   128     // recurrence CTAs (all resident on 148 SMs)
#define RPB  16      // rows of W_hh per CTA
#define RTHR 256

// ---------------- scratch + sync state (no allocations allowed) -------------
__device__ float g_pre[(size_t)T_DIM * N_DIM];   // 64 MB: pre = X@W_ih^T + b
__device__ float g_h0[N_DIM];                    // static zeros -> h_{-1}
__device__ unsigned g_cnt[T_DIM];                // per-step arrival counters

__global__ void init_cnt_kernel() {
    for (int i = threadIdx.x; i < T_DIM; i += blockDim.x) g_cnt[i] = 0u;
}

// ---------------- Kernel A: pre = X @ W_ih^T + (b_ih + b_hh) ----------------
// 128x128 tile, BK=8, 256 threads, 8x8 microtile, f32x2-packed inner loop.
__global__ __launch_bounds__(256) void gemm_pre_kernel(
    const float* __restrict__ X,
    const float* __restrict__ Wih,
    const float* __restrict__ b_ih,
    const float* __restrict__ b_hh)
{
    __shared__ float As[8][128];
    __shared__ float Bs[8][128];

    const int tx   = threadIdx.x;
    const int row0 = blockIdx.y * 128;   // t tile
    const int col0 = blockIdx.x * 128;   // n tile

    const int lr = tx >> 1;
    const int lc = (tx & 1) << 2;
    const int trow = (tx >> 4) << 3;
    const int tcol = (tx & 15) << 3;

    // acc2[i][j] = packed pair (cols 2j, 2j+1) for microtile row i
    unsigned long long acc2[8][4];
#pragma unroll
    for (int i = 0; i < 8; i++)
#pragma unroll
        for (int j = 0; j < 4; j++) acc2[i][j] = 0ull;

    const float* Xp = X   + (size_t)(row0 + lr) * M_DIM + lc;
    const float* Wp = Wih + (size_t)(col0 + lr) * M_DIM + lc;

    for (int k0 = 0; k0 < M_DIM; k0 += 8) {
        float4 a = *(const float4*)(Xp + k0);
        float4 b = *(const float4*)(Wp + k0);
        As[lc + 0][lr] = a.x; As[lc + 1][lr] = a.y;
        As[lc + 2][lr] = a.z; As[lc + 3][lr] = a.w;
        Bs[lc + 0][lr] = b.x; Bs[lc + 1][lr] = b.y;
        Bs[lc + 2][lr] = b.z; Bs[lc + 3][lr] = b.w;
        __syncthreads();

#pragma unroll
        for (int k = 0; k < 8; k++) {
            float ar[8];
#pragma unroll
            for (int i = 0; i < 8; i++) ar[i] = As[k][trow + i];
            const unsigned long long* bp =
                (const unsigned long long*)&Bs[k][tcol];   // 32B-aligned
            unsigned long long br2[4] = { bp[0], bp[1], bp[2], bp[3] };
#pragma unroll
            for (int i = 0; i < 8; i++) {
                unsigned long long ap;
                asm("mov.b64 %0, {%1, %1};" : "=l"(ap) : "f"(ar[i]));
#pragma unroll
                for (int j = 0; j < 4; j++)
                    asm("fma.rn.f32x2 %0, %1, %2, %3;"
                        : "=l"(acc2[i][j]) : "l"(ap), "l"(br2[j]), "l"(acc2[i][j]));
            }
        }
        __syncthreads();
    }

    float bias[8];
#pragma unroll
    for (int j = 0; j < 8; j++)
        bias[j] = b_ih[col0 + tcol + j] + b_hh[col0 + tcol + j];

#pragma unroll
    for (int i = 0; i < 8; i++) {
        float out8[8];
#pragma unroll
        for (int j = 0; j < 4; j++) {
            float lo, hi;
            asm("mov.b64 {%0, %1}, %2;" : "=f"(lo), "=f"(hi) : "l"(acc2[i][j]));
            out8[2 * j]     = lo + bias[2 * j];
            out8[2 * j + 1] = hi + bias[2 * j + 1];
        }
        float4* out = (float4*)&g_pre[(size_t)(row0 + trow + i) * N_DIM + col0 + tcol];
        out[0] = make_float4(out8[0], out8[1], out8[2], out8[3]);
        out[1] = make_float4(out8[4], out8[5], out8[6], out8[7]);
    }
}

// ---------------- fast tanh (MUFU.EX2 based, ~1e-7 rel err) -----------------
__device__ __forceinline__ float fast_tanh(float x) {
    float e = __expf(-2.0f * x);            // EX2; saturates cleanly
    return __fdividef(2.0f, 1.0f + e) - 1.0f;
}

// ---------------- Kernel B: persistent recurrence ---------------------------
// CTA b owns rows [16b,16b+16) of W_hh in registers as packed f32x2 pairs.
// Barrier: tid0 ONLY acquire-polls g_cnt[t-1]==128 (128 poll streams chip-wide,
// not 1024 -> no LTS-slice queueing), then __syncthreads fans out the
// happens-before edge to the whole CTA.
__global__ __launch_bounds__(RTHR, 1) void recur_kernel(
    const float* __restrict__ Whh,
    float* __restrict__ Y)
{
    const int tid  = threadIdx.x;
    const int base = blockIdx.x * RPB;
    const int warp = tid >> 5;
    const int lane = tid & 31;

    // Weights: thread holds W_hh[base+r][8*tid .. 8*tid+7] as 4 f32x2 packs.
    unsigned long long w2[RPB][4];
#pragma unroll
    for (int r = 0; r < RPB; r++) {
        const ulonglong2* p =
            (const ulonglong2*)&Whh[(size_t)(base + r) * N_DIM + tid * 8];
        ulonglong2 a = p[0], b = p[1];
        w2[r][0] = a.x; w2[r][1] = a.y; w2[r][2] = b.x; w2[r][3] = b.y;
    }

    __shared__ float part[RPB][RTHR];   // 16 KB

    for (int t = 0; t < T_DIM; t++) {
        // Prefetch pre for this warp's two rows (h-independent).
        const float2 pre2 =
            *(const float2*)&g_pre[(size_t)t * N_DIM + base + 2 * warp];

        // Single-poller barrier: wait until all 128 CTAs finished step t-1.
        if (t > 0) {
            if (tid == 0) {
                const unsigned* cp = &g_cnt[t - 1];
                unsigned c;
                do {
                    asm volatile("ld.acquire.gpu.global.u32 %0, [%1];"
                                 : "=r"(c) : "l"(cp) : "memory");
                } while (c < (unsigned)GR);
            }
            __syncthreads();   // extends tid0's acquire to all threads
        }

        const float* hp = (t == 0) ? g_h0 : (Y + (size_t)(t - 1) * N_DIM);
        const ulonglong2* hq = (const ulonglong2*)(hp + tid * 8);
        ulonglong2 ha = hq[0], hb = hq[1];
        unsigned long long h2[4] = { ha.x, ha.y, hb.x, hb.y };

#pragma unroll
        for (int r = 0; r < RPB; r++) {
            unsigned long long acc;
            asm("mul.rn.f32x2 %0, %1, %2;"
                : "=l"(acc) : "l"(w2[r][0]), "l"(h2[0]));
            asm("fma.rn.f32x2 %0, %1, %2, %3;"
                : "=l"(acc) : "l"(w2[r][1]), "l"(h2[1]), "l"(acc));
            asm("fma.rn.f32x2 %0, %1, %2, %3;"
                : "=l"(acc) : "l"(w2[r][2]), "l"(h2[2]), "l"(acc));
            asm("fma.rn.f32x2 %0, %1, %2, %3;"
                : "=l"(acc) : "l"(w2[r][3]), "l"(h2[3]), "l"(acc));
            float lo, hi;
            asm("mov.b64 {%0, %1}, %2;" : "=f"(lo), "=f"(hi) : "l"(acc));
            part[r][tid] = lo + hi;
        }
        __syncthreads();

        // Warp w reduces rows 2w, 2w+1 (interleaved; bfly shuffles).
        float s0, s1;
        {
            const int r0 = 2 * warp;
            float4 x0 = *(const float4*)&part[r0][lane * 4];
            float4 y0 = *(const float4*)&part[r0][128 + lane * 4];
            float4 x1 = *(const float4*)&part[r0 + 1][lane * 4];
            float4 y1 = *(const float4*)&part[r0 + 1][128 + lane * 4];
            s0 = ((x0.x + x0.y) + (x0.z + x0.w)) + ((y0.x + y0.y) + (y0.z + y0.w));
            s1 = ((x1.x + x1.y) + (x1.z + x1.w)) + ((y1.x + y1.y) + (y1.z + y1.w));
        }
#pragma unroll
        for (int o = 16; o > 0; o >>= 1) {
            s0 += __shfl_xor_sync(0xffffffffu, s0, o);
            s1 += __shfl_xor_sync(0xffffffffu, s1, o);
        }

        if (lane == 0) {
            float2 v;
            v.x = fast_tanh(s0 + pre2.x);
            v.y = fast_tanh(s1 + pre2.y);
            *(float2*)&Y[(size_t)t * N_DIM + base + 2 * warp] = v;
        }

        __syncthreads();     // all warps' Y stores for step t are done

        if (tid == 0) {
            asm volatile("red.release.gpu.global.add.u32 [%0], %1;"
                         :: "l"(&g_cnt[t]), "r"(1u) : "memory");
        }
    }
}

// ---------------- launch ----------------------------------------------------
extern "C" void kernel_launch(void* const* d_in, const int* in_sizes, int n_in,
                              void* d_out, int out_size)
{
    const float* X    = (const float*)d_in[0];  // (T, M)
    const float* Wih  = (const float*)d_in[1];  // (N, M)
    const float* Whh  = (const float*)d_in[2];  // (N, N)
    const float* b_ih = (const float*)d_in[3];  // (N,)
    const float* b_hh = (const float*)d_in[4];  // (N,)
    float* Y = (float*)d_out;                   // (T, N)

    init_cnt_kernel<<<1, 256>>>();

    dim3 ggrid(N_DIM / 128, T_DIM / 128);       // (16, 64)
    gemm_pre_kernel<<<ggrid, 256>>>(X, Wih, b_ih, b_hh);

    recur_kernel<<<GR, RTHR>>>(Whh, Y);
}